// round 3
// baseline (speedup 1.0000x reference)
#include <cuda_runtime.h>
#include <math.h>

#define NN   50000
#define EE   800000
#define FF   128
#define HIDD 128
#define NHH  8
#define NLL  3
#define NGG  64
#define NCC  3

// ---------------- scratch (static device globals; no allocation) ----------------
__device__ float    g_h [(size_t)NN*HIDD];        // current node features
__device__ float    g_hn[(size_t)NN*HIDD];        // GAT accumulator / next features
__device__ float    g_xl[(size_t)NN*NHH*HIDD];    // per-layer lin output [N, 8, 128]
__device__ float    g_as[(size_t)NN*NHH];         // alpha_src
__device__ float    g_ad[(size_t)NN*NHH];         // alpha_dst
__device__ unsigned g_emax[(size_t)NN*NHH];       // encoded segment max
__device__ float    g_den[(size_t)NN*NHH];        // softmax denominators
__device__ float    g_gi[(size_t)NN*3*HIDD];      // GRU input gates
__device__ float    g_gh[(size_t)NN*3*HIDD];      // GRU hidden gates
__device__ float    g_pool[NGG*HIDD];             // pooled sums
__device__ float    g_cnt [NGG];                  // group counts

// ---------------- GEMM: C[M,Nout] = act(A[M,128] @ B + bias) --------------------
// BT=false: B is [128, Nout] row-major.  BT=true: B is [Nout, 128] row-major (B^T).
// BM=128, BN=128, BK=8, 256 threads, 8x8 microtile.
template<int ACT, bool BT>
__global__ __launch_bounds__(256) void gemm_k128(
    const float* __restrict__ A, const float* __restrict__ B,
    const float* __restrict__ bias, float* __restrict__ C,
    int M, int Nout)
{
    __shared__ float As[8][128];
    __shared__ float Bs[8][128];
    const int tid = threadIdx.x;
    const int tx = tid & 15, ty = tid >> 4;
    const int m0 = blockIdx.y * 128;
    const int n0 = blockIdx.x * 128;

    float acc[8][8];
    #pragma unroll
    for (int i = 0; i < 8; i++)
        #pragma unroll
        for (int j = 0; j < 8; j++) acc[i][j] = 0.f;

    const int am = tid >> 1, ak = (tid & 1) * 4;   // A / BT loader mapping
    const int bk = tid >> 5, bn = (tid & 31) * 4;  // non-T B loader mapping

    for (int k0 = 0; k0 < 128; k0 += 8) {
        float4 av = make_float4(0.f, 0.f, 0.f, 0.f);
        if (m0 + am < M)
            av = *(const float4*)(A + (size_t)(m0 + am) * 128 + k0 + ak);
        As[ak + 0][am] = av.x; As[ak + 1][am] = av.y;
        As[ak + 2][am] = av.z; As[ak + 3][am] = av.w;
        if (BT) {
            float4 bv = *(const float4*)(B + (size_t)(n0 + am) * 128 + k0 + ak);
            Bs[ak + 0][am] = bv.x; Bs[ak + 1][am] = bv.y;
            Bs[ak + 2][am] = bv.z; Bs[ak + 3][am] = bv.w;
        } else {
            float4 bv = *(const float4*)(B + (size_t)(k0 + bk) * Nout + n0 + bn);
            *(float4*)&Bs[bk][bn] = bv;
        }
        __syncthreads();
        #pragma unroll
        for (int k = 0; k < 8; k++) {
            float a[8], b[8];
            float4 t;
            t = *(float4*)&As[k][ty * 8];     a[0]=t.x; a[1]=t.y; a[2]=t.z; a[3]=t.w;
            t = *(float4*)&As[k][ty * 8 + 4]; a[4]=t.x; a[5]=t.y; a[6]=t.z; a[7]=t.w;
            t = *(float4*)&Bs[k][tx * 8];     b[0]=t.x; b[1]=t.y; b[2]=t.z; b[3]=t.w;
            t = *(float4*)&Bs[k][tx * 8 + 4]; b[4]=t.x; b[5]=t.y; b[6]=t.z; b[7]=t.w;
            #pragma unroll
            for (int i = 0; i < 8; i++)
                #pragma unroll
                for (int j = 0; j < 8; j++)
                    acc[i][j] += a[i] * b[j];
        }
        __syncthreads();
    }

    #pragma unroll
    for (int i = 0; i < 8; i++) {
        int row = m0 + ty * 8 + i;
        if (row >= M) continue;
        int col = n0 + tx * 8;
        float vb[8];
        #pragma unroll
        for (int j = 0; j < 8; j++) {
            float v = acc[i][j] + (bias ? bias[col + j] : 0.f);
            if (ACT == 1) v = fmaxf(v, 0.f);
            vb[j] = v;
        }
        *(float4*)(C + (size_t)row * Nout + col)     = make_float4(vb[0], vb[1], vb[2], vb[3]);
        *(float4*)(C + (size_t)row * Nout + col + 4) = make_float4(vb[4], vb[5], vb[6], vb[7]);
    }
}

// ---------------- per-node attention logits (warp per node) ---------------------
__global__ void alpha_kernel(const float* __restrict__ xl,
                             const float* __restrict__ wsrc,
                             const float* __restrict__ wdst,
                             float* __restrict__ outs, float* __restrict__ outd)
{
    int warp = (blockIdx.x * blockDim.x + threadIdx.x) >> 5;
    int lane = threadIdx.x & 31;
    if (warp >= NN) return;
    const float4* xr = (const float4*)(xl + (size_t)warp * NHH * HIDD);
    #pragma unroll
    for (int h = 0; h < NHH; h++) {
        float4 xv = xr[h * 32 + lane];
        float4 ws = *(const float4*)(wsrc + h * HIDD + lane * 4);
        float4 wd = *(const float4*)(wdst + h * HIDD + lane * 4);
        float ss = xv.x*ws.x + xv.y*ws.y + xv.z*ws.z + xv.w*ws.w;
        float sd = xv.x*wd.x + xv.y*wd.y + xv.z*wd.z + xv.w*wd.w;
        #pragma unroll
        for (int o = 16; o; o >>= 1) {
            ss += __shfl_xor_sync(0xffffffffu, ss, o);
            sd += __shfl_xor_sync(0xffffffffu, sd, o);
        }
        if (lane == 0) { outs[(size_t)warp*NHH + h] = ss; outd[(size_t)warp*NHH + h] = sd; }
    }
}

// order-preserving float<->uint encoding for atomicMax
__device__ __forceinline__ unsigned fenc(float f) {
    unsigned u = __float_as_uint(f);
    return (u & 0x80000000u) ? ~u : (u | 0x80000000u);
}
__device__ __forceinline__ float fdec(unsigned e) {
    return (e & 0x80000000u) ? __uint_as_float(e ^ 0x80000000u) : __uint_as_float(~e);
}

// edge ids >= EE are the appended self-loops (src = dst = e - EE)
__device__ __forceinline__ void edge_sd(const int* ei, int e, int& s, int& d) {
    if (e < EE) { s = ei[e]; d = ei[EE + e]; }
    else        { s = e - EE; d = s; }
}

__global__ void edge_max(const int* __restrict__ ei,
                         const float* __restrict__ as_, const float* __restrict__ ad_,
                         unsigned* __restrict__ emax)
{
    int e = blockIdx.x * blockDim.x + threadIdx.x;
    if (e >= EE + NN) return;
    int s, d; edge_sd(ei, e, s, d);
    float4 s0 = *(const float4*)(as_ + (size_t)s*8);
    float4 s1 = *(const float4*)(as_ + (size_t)s*8 + 4);
    float4 d0 = *(const float4*)(ad_ + (size_t)d*8);
    float4 d1 = *(const float4*)(ad_ + (size_t)d*8 + 4);
    float v[8] = {s0.x+d0.x, s0.y+d0.y, s0.z+d0.z, s0.w+d0.w,
                  s1.x+d1.x, s1.y+d1.y, s1.z+d1.z, s1.w+d1.w};
    #pragma unroll
    for (int h = 0; h < 8; h++) {
        float t = v[h] > 0.f ? v[h] : 0.2f * v[h];
        atomicMax(&emax[(size_t)d*8 + h], fenc(t));
    }
}

__global__ void edge_den(const int* __restrict__ ei,
                         const float* __restrict__ as_, const float* __restrict__ ad_,
                         const unsigned* __restrict__ emax, float* __restrict__ den)
{
    int e = blockIdx.x * blockDim.x + threadIdx.x;
    if (e >= EE + NN) return;
    int s, d; edge_sd(ei, e, s, d);
    float4 s0 = *(const float4*)(as_ + (size_t)s*8);
    float4 s1 = *(const float4*)(as_ + (size_t)s*8 + 4);
    float4 d0 = *(const float4*)(ad_ + (size_t)d*8);
    float4 d1 = *(const float4*)(ad_ + (size_t)d*8 + 4);
    float v[8] = {s0.x+d0.x, s0.y+d0.y, s0.z+d0.z, s0.w+d0.w,
                  s1.x+d1.x, s1.y+d1.y, s1.z+d1.z, s1.w+d1.w};
    #pragma unroll
    for (int h = 0; h < 8; h++) {
        float t = v[h] > 0.f ? v[h] : 0.2f * v[h];
        float m = fdec(emax[(size_t)d*8 + h]);
        atomicAdd(&den[(size_t)d*8 + h], __expf(t - m));
    }
}

// warp per edge: acc[dst,c] += sum_h w_h * xl[src,h,c]
__global__ void edge_msg(const int* __restrict__ ei,
                         const float* __restrict__ as_, const float* __restrict__ ad_,
                         const unsigned* __restrict__ emax, const float* __restrict__ den,
                         const float* __restrict__ xl, float* __restrict__ acc)
{
    int gw = (blockIdx.x * blockDim.x + threadIdx.x) >> 5;
    int lane = threadIdx.x & 31;
    if (gw >= EE + NN) return;
    int s, d; edge_sd(ei, gw, s, d);
    float w = 0.f;
    if (lane < 8) {
        float v = as_[(size_t)s*8 + lane] + ad_[(size_t)d*8 + lane];
        v = v > 0.f ? v : 0.2f * v;
        float m = fdec(emax[(size_t)d*8 + lane]);
        w = __expf(v - m) / (den[(size_t)d*8 + lane] + 1e-16f);
    }
    const float4* xr = (const float4*)(xl + (size_t)s * NHH * HIDD);
    float4 r = make_float4(0.f, 0.f, 0.f, 0.f);
    #pragma unroll
    for (int h = 0; h < 8; h++) {
        float wh = __shfl_sync(0xffffffffu, w, h);
        float4 xv = xr[h * 32 + lane];
        r.x += wh * xv.x; r.y += wh * xv.y; r.z += wh * xv.z; r.w += wh * xv.w;
    }
    float* o = acc + (size_t)d * HIDD + lane * 4;
    atomicAdd(o + 0, r.x); atomicAdd(o + 1, r.y);
    atomicAdd(o + 2, r.z); atomicAdd(o + 3, r.w);
}

__global__ void gat_finish(const float* __restrict__ acc, const float* __restrict__ bias,
                           float* __restrict__ hout, int do_relu)
{
    size_t i = (size_t)blockIdx.x * blockDim.x + threadIdx.x;
    if (i >= (size_t)NN * HIDD) return;
    int c = (int)(i & 127);
    float v = acc[i] * (1.f / NHH) + bias[c];
    if (do_relu) v = fmaxf(v, 0.f);
    hout[i] = v;
}

__global__ void gru_kernel(const float* __restrict__ gi, const float* __restrict__ gh,
                           const float* __restrict__ mem, float* __restrict__ hout)
{
    size_t i = (size_t)blockIdx.x * blockDim.x + threadIdx.x;
    if (i >= (size_t)NN * HIDD) return;
    size_t n = i >> 7; int c = (int)(i & 127);
    const float* a = gi + n * 384;
    const float* b = gh + n * 384;
    float r  = 1.f / (1.f + __expf(-(a[c]       + b[c])));
    float z  = 1.f / (1.f + __expf(-(a[128 + c] + b[128 + c])));
    float nc = tanhf(a[256 + c] + r * b[256 + c]);
    hout[i] = (1.f - z) * nc + z * mem[i];
}

// batch ids are sorted -> per-block run-length accumulation, few atomics
__global__ void pool_kernel(const float* __restrict__ h, const int* __restrict__ batch,
                            float* __restrict__ sums, float* __restrict__ cnt)
{
    const int CHUNK = 500;
    int start = blockIdx.x * CHUNK;
    if (start >= NN) return;
    int end = min(start + CHUNK, NN);
    int c = threadIdx.x;
    int g = batch[start];
    float acc = 0.f, count = 0.f;
    for (int n = start; n < end; n++) {
        int bg = batch[n];
        if (bg != g) {
            atomicAdd(&sums[g * HIDD + c], acc);
            if (c == 0) atomicAdd(&cnt[g], count);
            acc = 0.f; count = 0.f; g = bg;
        }
        acc += h[(size_t)n * HIDD + c];
        count += 1.f;
    }
    atomicAdd(&sums[g * HIDD + c], acc);
    if (c == 0) atomicAdd(&cnt[g], count);
}

// pooled mean -> MLP -> logits -> softmax; writes all three outputs
__global__ void classifier_kernel(const float* __restrict__ sums, const float* __restrict__ cnt,
                                  const float* __restrict__ c1W, const float* __restrict__ c1b,
                                  const float* __restrict__ c2W, const float* __restrict__ c2b,
                                  float* __restrict__ out)
{
    __shared__ float p[HIDD];
    __shared__ float hid[64];
    __shared__ float lg[3];
    int g = blockIdx.x, t = threadIdx.x;
    float c = fmaxf(cnt[g], 1.f);
    float pv = sums[g * HIDD + t] / c;
    p[t] = pv;
    out[NGG * NCC + g * HIDD + t] = pv;                       // pooled
    __syncthreads();
    if (t < 64) {
        float s = c1b[t];
        #pragma unroll 4
        for (int k = 0; k < HIDD; k++) s += p[k] * c1W[k * 64 + t];
        hid[t] = fmaxf(s, 0.f);
    }
    __syncthreads();
    if (t < 3) {
        float s = c2b[t];
        #pragma unroll 4
        for (int k = 0; k < 64; k++) s += hid[k] * c2W[k * 3 + t];
        lg[t] = s;
        out[g * NCC + t] = s;                                  // logits
    }
    __syncthreads();
    if (t < 3) {
        float mx = fmaxf(fmaxf(lg[0], lg[1]), lg[2]);
        float e0 = expf(lg[0] - mx), e1 = expf(lg[1] - mx), e2 = expf(lg[2] - mx);
        float ev = (t == 0) ? e0 : ((t == 1) ? e1 : e2);
        out[NGG * NCC + NGG * HIDD + g * NCC + t] = ev / (e0 + e1 + e2);  // preds
    }
}

// --------------------------------- host -----------------------------------------
extern "C" void kernel_launch(void* const* d_in, const int* in_sizes, int n_in,
                              void* d_out, int out_size)
{
    const float* x      = (const float*)d_in[0];
    const int*   ei     = (const int*)d_in[1];      // int32 (JAX x64 disabled)
    const int*   batch  = (const int*)d_in[2];      // int32
    const float* memory = (const float*)d_in[3];
    const float* enc_W  = (const float*)d_in[4];
    const float* enc_b  = (const float*)d_in[5];
    const float* gat_W  = (const float*)d_in[6];
    const float* att_s  = (const float*)d_in[7];
    const float* att_d  = (const float*)d_in[8];
    const float* gat_b  = (const float*)d_in[9];
    const float* W_ih   = (const float*)d_in[10];
    const float* W_hh   = (const float*)d_in[11];
    const float* b_ih   = (const float*)d_in[12];
    const float* b_hh   = (const float*)d_in[13];
    const float* c1W    = (const float*)d_in[14];
    const float* c1b    = (const float*)d_in[15];
    const float* c2W    = (const float*)d_in[16];
    const float* c2b    = (const float*)d_in[17];
    float* out = (float*)d_out;

    float *p_h, *p_hn, *p_xl, *p_as, *p_ad, *p_den, *p_gi, *p_gh, *p_pool, *p_cnt;
    unsigned* p_emax;
    cudaGetSymbolAddress((void**)&p_h,   g_h);
    cudaGetSymbolAddress((void**)&p_hn,  g_hn);
    cudaGetSymbolAddress((void**)&p_xl,  g_xl);
    cudaGetSymbolAddress((void**)&p_as,  g_as);
    cudaGetSymbolAddress((void**)&p_ad,  g_ad);
    cudaGetSymbolAddress((void**)&p_emax, g_emax);
    cudaGetSymbolAddress((void**)&p_den, g_den);
    cudaGetSymbolAddress((void**)&p_gi,  g_gi);
    cudaGetSymbolAddress((void**)&p_gh,  g_gh);
    cudaGetSymbolAddress((void**)&p_pool, g_pool);
    cudaGetSymbolAddress((void**)&p_cnt, g_cnt);

    const int MB = (NN + 127) / 128;   // 391 row-blocks
    const int ETOT = EE + NN;

    // node encoder: h = relu(x @ enc_W + enc_b)
    gemm_k128<1, false><<<dim3(1, MB), 256>>>(x, enc_W, enc_b, p_h, NN, HIDD);

    for (int l = 0; l < NLL; l++) {
        gemm_k128<0, false><<<dim3(8, MB), 256>>>(
            p_h, gat_W + (size_t)l * HIDD * NHH * HIDD, nullptr, p_xl, NN, NHH * HIDD);
        alpha_kernel<<<(NN * 32 + 255) / 256, 256>>>(
            p_xl, att_s + l * NHH * HIDD, att_d + l * NHH * HIDD, p_as, p_ad);
        cudaMemsetAsync(p_emax, 0, sizeof(unsigned) * (size_t)NN * NHH);
        cudaMemsetAsync(p_den,  0, sizeof(float) * (size_t)NN * NHH);
        cudaMemsetAsync(p_hn,   0, sizeof(float) * (size_t)NN * HIDD);
        edge_max<<<(ETOT + 255) / 256, 256>>>(ei, p_as, p_ad, p_emax);
        edge_den<<<(ETOT + 255) / 256, 256>>>(ei, p_as, p_ad, p_emax, p_den);
        edge_msg<<<((size_t)ETOT * 32 + 255) / 256, 256>>>(
            ei, p_as, p_ad, p_emax, p_den, p_xl, p_hn);
        gat_finish<<<((size_t)NN * HIDD + 255) / 256, 256>>>(
            p_hn, gat_b + l * HIDD, p_h, (l < NLL - 1) ? 1 : 0);
    }

    // GRU
    gemm_k128<0, true><<<dim3(3, MB), 256>>>(p_h,    W_ih, b_ih, p_gi, NN, 3 * HIDD);
    gemm_k128<0, true><<<dim3(3, MB), 256>>>(memory, W_hh, b_hh, p_gh, NN, 3 * HIDD);
    gru_kernel<<<((size_t)NN * HIDD + 255) / 256, 256>>>(p_gi, p_gh, memory, p_h);

    // pooling + classifier
    cudaMemsetAsync(p_pool, 0, sizeof(float) * NGG * HIDD);
    cudaMemsetAsync(p_cnt,  0, sizeof(float) * NGG);
    pool_kernel<<<(NN + 499) / 500, 128>>>(p_h, batch, p_pool, p_cnt);
    classifier_kernel<<<NGG, HIDD>>>(p_pool, p_cnt, c1W, c1b, c2W, c2b, out);
}

// round 4
// speedup vs baseline: 1.6352x; 1.6352x over previous
#include <cuda_runtime.h>
#include <math.h>

#define NN   50000
#define EE   800000
#define ETOT (EE + NN)
#define HIDD 128
#define NHH  8
#define NLL  3
#define NGG  64
#define NCC  3

// ---------------- scratch (static device globals) ----------------
__device__ float g_h [(size_t)NN*HIDD];          // node features
__device__ float g_z [(size_t)NN*NHH*HIDD];      // aggregated z [N, 8*128]
__device__ float g_as[(size_t)NN*NHH];           // alpha_src
__device__ float g_ad[(size_t)NN*NHH];           // alpha_dst
__device__ float g_q [16*HIDD];                  // qT [16][128]
__device__ float g_wt[(size_t)NHH*HIDD*HIDD];    // Wt [1024,128]
__device__ float g_gi[(size_t)NN*3*HIDD];
__device__ float g_gh[(size_t)NN*3*HIDD];
__device__ float g_pool[NGG*HIDD];
__device__ float g_cnt [NGG];
__device__ int   g_deg [NN];
__device__ int   g_off [NN+1];
__device__ int   g_cur [NN];
__device__ int   g_esrc[ETOT];

// ---------------- CSR build (dst-grouped, src payload) ----------------
__global__ void csr_count(const int* __restrict__ ei, int* __restrict__ deg)
{
    int e = blockIdx.x * blockDim.x + threadIdx.x;
    if (e >= ETOT) return;
    int d = (e < EE) ? ei[EE + e] : (e - EE);
    atomicAdd(&deg[d], 1);
}

__global__ __launch_bounds__(1024) void csr_scan(const int* __restrict__ deg,
                                                 int* __restrict__ off)
{
    const int CHK = (NN + 1023) / 1024;   // 49
    int t = threadIdx.x;
    int lo = t * CHK, hi = min(lo + CHK, NN);
    int s = 0;
    for (int i = lo; i < hi; i++) s += deg[i];
    __shared__ int ps[1024];
    ps[t] = s; __syncthreads();
    for (int o = 1; o < 1024; o <<= 1) {
        int v = (t >= o) ? ps[t - o] : 0;
        __syncthreads();
        ps[t] += v;
        __syncthreads();
    }
    int run = (t > 0) ? ps[t - 1] : 0;
    for (int i = lo; i < hi; i++) { off[i] = run; run += deg[i]; }
    if (t == 1023) off[NN] = run;
}

__global__ void csr_scatter(const int* __restrict__ ei, const int* __restrict__ off,
                            int* __restrict__ cur, int* __restrict__ esrc)
{
    int e = blockIdx.x * blockDim.x + threadIdx.x;
    if (e >= ETOT) return;
    int s, d;
    if (e < EE) { s = ei[e]; d = ei[EE + e]; }
    else        { s = e - EE; d = s; }
    int p = atomicAdd(&cur[d], 1);
    esrc[off[d] + p] = s;
}

// ---------------- double-buffered SGEMM --------------------------------
// C[M,Nout] = relu?( scale * (A[M,K] @ B) + bias )
// BT=false: B[K,Nout]; BT=true: B[Nout,K]. BM=BN=128, BK=16, 256 thr, 8x8 micro.
template<bool BT>
__global__ __launch_bounds__(256) void gemm_db(
    const float* __restrict__ A, const float* __restrict__ B,
    const float* __restrict__ bias, float* __restrict__ C,
    int M, int K, int Nout, float scale, int relu)
{
    __shared__ float As[2][16][128];
    __shared__ float Bs[2][16][128];
    const int tid = threadIdx.x;
    const int tx = tid & 15, ty = tid >> 4;
    const int m0 = blockIdx.y * 128;
    const int n0 = blockIdx.x * 128;

    float acc[8][8];
    #pragma unroll
    for (int i = 0; i < 8; i++)
        #pragma unroll
        for (int j = 0; j < 8; j++) acc[i][j] = 0.f;

    float4 ra[2], rb[2];
    const int nst = K >> 4;

    // prologue: load stage 0
    #pragma unroll
    for (int j = 0; j < 2; j++) {
        int v = tid * 2 + j;
        int row = v >> 2, kq = v & 3;
        ra[j] = make_float4(0.f, 0.f, 0.f, 0.f);
        if (m0 + row < M) ra[j] = *(const float4*)(A + (size_t)(m0 + row) * K + kq * 4);
        if (BT) {
            rb[j] = *(const float4*)(B + (size_t)(n0 + row) * K + kq * 4);
        } else {
            int k = v >> 5, c = (v & 31) * 4;
            rb[j] = *(const float4*)(B + (size_t)k * Nout + n0 + c);
        }
    }
    #pragma unroll
    for (int j = 0; j < 2; j++) {
        int v = tid * 2 + j;
        int row = v >> 2, kq = v & 3;
        As[0][kq*4+0][row] = ra[j].x; As[0][kq*4+1][row] = ra[j].y;
        As[0][kq*4+2][row] = ra[j].z; As[0][kq*4+3][row] = ra[j].w;
        if (BT) {
            Bs[0][kq*4+0][row] = rb[j].x; Bs[0][kq*4+1][row] = rb[j].y;
            Bs[0][kq*4+2][row] = rb[j].z; Bs[0][kq*4+3][row] = rb[j].w;
        } else {
            int k = v >> 5, c = (v & 31) * 4;
            *(float4*)&Bs[0][k][c] = rb[j];
        }
    }
    __syncthreads();

    for (int s = 0; s < nst; s++) {
        const int buf = s & 1;
        if (s + 1 < nst) {
            int k0 = (s + 1) * 16;
            #pragma unroll
            for (int j = 0; j < 2; j++) {
                int v = tid * 2 + j;
                int row = v >> 2, kq = v & 3;
                ra[j] = make_float4(0.f, 0.f, 0.f, 0.f);
                if (m0 + row < M) ra[j] = *(const float4*)(A + (size_t)(m0 + row) * K + k0 + kq * 4);
                if (BT) {
                    rb[j] = *(const float4*)(B + (size_t)(n0 + row) * K + k0 + kq * 4);
                } else {
                    int k = v >> 5, c = (v & 31) * 4;
                    rb[j] = *(const float4*)(B + (size_t)(k0 + k) * Nout + n0 + c);
                }
            }
        }
        #pragma unroll
        for (int k = 0; k < 16; k++) {
            float a[8], b[8];
            float4 t;
            t = *(float4*)&As[buf][k][ty * 8];     a[0]=t.x; a[1]=t.y; a[2]=t.z; a[3]=t.w;
            t = *(float4*)&As[buf][k][ty * 8 + 4]; a[4]=t.x; a[5]=t.y; a[6]=t.z; a[7]=t.w;
            t = *(float4*)&Bs[buf][k][tx * 8];     b[0]=t.x; b[1]=t.y; b[2]=t.z; b[3]=t.w;
            t = *(float4*)&Bs[buf][k][tx * 8 + 4]; b[4]=t.x; b[5]=t.y; b[6]=t.z; b[7]=t.w;
            #pragma unroll
            for (int i = 0; i < 8; i++)
                #pragma unroll
                for (int j = 0; j < 8; j++)
                    acc[i][j] += a[i] * b[j];
        }
        if (s + 1 < nst) {
            const int nbuf = buf ^ 1;
            #pragma unroll
            for (int j = 0; j < 2; j++) {
                int v = tid * 2 + j;
                int row = v >> 2, kq = v & 3;
                As[nbuf][kq*4+0][row] = ra[j].x; As[nbuf][kq*4+1][row] = ra[j].y;
                As[nbuf][kq*4+2][row] = ra[j].z; As[nbuf][kq*4+3][row] = ra[j].w;
                if (BT) {
                    Bs[nbuf][kq*4+0][row] = rb[j].x; Bs[nbuf][kq*4+1][row] = rb[j].y;
                    Bs[nbuf][kq*4+2][row] = rb[j].z; Bs[nbuf][kq*4+3][row] = rb[j].w;
                } else {
                    int k = v >> 5, c = (v & 31) * 4;
                    *(float4*)&Bs[nbuf][k][c] = rb[j];
                }
            }
        }
        __syncthreads();
    }

    #pragma unroll
    for (int i = 0; i < 8; i++) {
        int row = m0 + ty * 8 + i;
        if (row >= M) continue;
        int col = n0 + tx * 8;
        float vb[8];
        #pragma unroll
        for (int j = 0; j < 8; j++) {
            float v = acc[i][j] * scale + (bias ? bias[col + j] : 0.f);
            if (relu) v = fmaxf(v, 0.f);
            vb[j] = v;
        }
        *(float4*)(C + (size_t)row * Nout + col)     = make_float4(vb[0], vb[1], vb[2], vb[3]);
        *(float4*)(C + (size_t)row * Nout + col + 4) = make_float4(vb[4], vb[5], vb[6], vb[7]);
    }
}

// ---------------- attention projection vectors -------------------------
// qT[j][k] (j<8: src head j, j>=8: dst head j-8) = sum_c W[k, h*128+c] * att[h,c]
__global__ void build_q(const float* __restrict__ W, const float* __restrict__ asrc,
                        const float* __restrict__ adst, float* __restrict__ qT)
{
    int w = (blockIdx.x * blockDim.x + threadIdx.x) >> 5;
    int lane = threadIdx.x & 31;
    if (w >= 2048) return;
    int j = w >> 7, k = w & 127;
    int h = j & 7;
    const float* att = ((j < 8) ? asrc : adst) + h * HIDD;
    const float* wr = W + (size_t)k * (NHH * HIDD) + h * HIDD;
    float4 a = *(const float4*)(wr + lane * 4);
    float4 b = *(const float4*)(att + lane * 4);
    float s = a.x*b.x + a.y*b.y + a.z*b.z + a.w*b.w;
    #pragma unroll
    for (int o = 16; o; o >>= 1) s += __shfl_xor_sync(0xffffffffu, s, o);
    if (lane == 0) qT[j * HIDD + k] = s;
}

// alpha = h @ qT^T : one warp per node, qT cached in smem as [16][128]
__global__ __launch_bounds__(256) void alpha2(const float* __restrict__ hf,
                                              const float* __restrict__ qT,
                                              float* __restrict__ as_, float* __restrict__ ad_)
{
    __shared__ float qs[16][HIDD];
    int t = threadIdx.x;
    for (int i = t; i < 16 * HIDD; i += 256) qs[i >> 7][i & 127] = qT[i];
    __syncthreads();
    int n = (blockIdx.x * 256 + t) >> 5;
    int lane = t & 31;
    if (n >= NN) return;
    float4 hv = *(const float4*)(hf + (size_t)n * HIDD + lane * 4);
    #pragma unroll
    for (int j = 0; j < 16; j++) {
        float4 qv = *(const float4*)&qs[j][lane * 4];
        float s = hv.x*qv.x + hv.y*qv.y + hv.z*qv.z + hv.w*qv.w;
        #pragma unroll
        for (int o = 16; o; o >>= 1) s += __shfl_xor_sync(0xffffffffu, s, o);
        if (lane == 0) {
            if (j < 8) as_[(size_t)n * 8 + j] = s;
            else       ad_[(size_t)n * 8 + (j - 8)] = s;
        }
    }
}

// Wt[h*128+k][c] = W[k][h*128+c]
__global__ void build_wt(const float* __restrict__ W, float* __restrict__ Wt)
{
    int idx = blockIdx.x * blockDim.x + threadIdx.x;
    if (idx >= NHH * HIDD * HIDD) return;
    int kk = idx >> 7, c = idx & 127;
    int h = kk >> 7, k = kk & 127;
    Wt[idx] = W[(size_t)k * (NHH * HIDD) + h * HIDD + c];
}

// ---------------- CSR edge aggregation: z[n,h,c] = sum_e softmax_w * h[src,c]
__global__ __launch_bounds__(128) void edge_agg(
    const int* __restrict__ off, const int* __restrict__ esrc,
    const float* __restrict__ as_, const float* __restrict__ ad_,
    const float* __restrict__ hf, float* __restrict__ zb)
{
    int n = blockIdx.x, t = threadIdx.x, h = t & 7;
    int e0 = off[n], e1 = off[n + 1];
    __shared__ float adn[8];
    __shared__ float den[8];
    __shared__ float red[16][8];
    __shared__ float ws[32][8];
    __shared__ int   ssm[32];
    if (t < 8) adn[t] = ad_[(size_t)n * 8 + t];
    __syncthreads();

    // denominators (exact softmax without max-shift: values are small)
    float part = 0.f;
    for (int i = e0 + (t >> 3); i < e1; i += 16) {
        int s = esrc[i];
        float v = as_[(size_t)s * 8 + h] + adn[h];
        v = v > 0.f ? v : 0.2f * v;
        part += __expf(v);
    }
    red[t >> 3][h] = part;
    __syncthreads();
    if (t < 8) {
        float x = 0.f;
        #pragma unroll
        for (int i = 0; i < 16; i++) x += red[i][t];
        den[t] = x;
    }
    __syncthreads();

    float z[8];
    #pragma unroll
    for (int i = 0; i < 8; i++) z[i] = 0.f;

    for (int c0 = e0; c0 < e1; c0 += 32) {
        int m = min(32, e1 - c0);
        for (int i = t >> 3; i < m; i += 16) {
            int s = esrc[c0 + i];
            if (h == 0) ssm[i] = s;
            float v = as_[(size_t)s * 8 + h] + adn[h];
            v = v > 0.f ? v : 0.2f * v;
            ws[i][h] = __expf(v) / (den[h] + 1e-16f);
        }
        __syncthreads();
        for (int i = 0; i < m; i++) {
            float val = hf[(size_t)ssm[i] * HIDD + t];
            #pragma unroll
            for (int hh = 0; hh < 8; hh++) z[hh] += ws[i][hh] * val;
        }
        __syncthreads();
    }
    float* zr = zb + (size_t)n * (NHH * HIDD) + t;
    #pragma unroll
    for (int hh = 0; hh < 8; hh++) zr[hh * HIDD] = z[hh];
}

// ---------------- GRU / pool / classifier ------------------------------
__global__ void gru_kernel(const float* __restrict__ gi, const float* __restrict__ gh,
                           const float* __restrict__ mem, float* __restrict__ hout)
{
    size_t i = (size_t)blockIdx.x * blockDim.x + threadIdx.x;
    if (i >= (size_t)NN * HIDD) return;
    size_t n = i >> 7; int c = (int)(i & 127);
    const float* a = gi + n * 384;
    const float* b = gh + n * 384;
    float r  = 1.f / (1.f + __expf(-(a[c]       + b[c])));
    float z  = 1.f / (1.f + __expf(-(a[128 + c] + b[128 + c])));
    float nc = tanhf(a[256 + c] + r * b[256 + c]);
    hout[i] = (1.f - z) * nc + z * mem[i];
}

__global__ void pool_kernel(const float* __restrict__ h, const int* __restrict__ batch,
                            float* __restrict__ sums, float* __restrict__ cnt)
{
    const int CHUNK = 500;
    int start = blockIdx.x * CHUNK;
    if (start >= NN) return;
    int end = min(start + CHUNK, NN);
    int c = threadIdx.x;
    int g = batch[start];
    float acc = 0.f, count = 0.f;
    for (int n = start; n < end; n++) {
        int bg = batch[n];
        if (bg != g) {
            atomicAdd(&sums[g * HIDD + c], acc);
            if (c == 0) atomicAdd(&cnt[g], count);
            acc = 0.f; count = 0.f; g = bg;
        }
        acc += h[(size_t)n * HIDD + c];
        count += 1.f;
    }
    atomicAdd(&sums[g * HIDD + c], acc);
    if (c == 0) atomicAdd(&cnt[g], count);
}

__global__ void classifier_kernel(const float* __restrict__ sums, const float* __restrict__ cnt,
                                  const float* __restrict__ c1W, const float* __restrict__ c1b,
                                  const float* __restrict__ c2W, const float* __restrict__ c2b,
                                  float* __restrict__ out)
{
    __shared__ float p[HIDD];
    __shared__ float hid[64];
    __shared__ float lg[3];
    int g = blockIdx.x, t = threadIdx.x;
    float c = fmaxf(cnt[g], 1.f);
    float pv = sums[g * HIDD + t] / c;
    p[t] = pv;
    out[NGG * NCC + g * HIDD + t] = pv;                       // pooled
    __syncthreads();
    if (t < 64) {
        float s = c1b[t];
        #pragma unroll 4
        for (int k = 0; k < HIDD; k++) s += p[k] * c1W[k * 64 + t];
        hid[t] = fmaxf(s, 0.f);
    }
    __syncthreads();
    if (t < 3) {
        float s = c2b[t];
        #pragma unroll 4
        for (int k = 0; k < 64; k++) s += hid[k] * c2W[k * 3 + t];
        lg[t] = s;
        out[g * NCC + t] = s;                                  // logits
    }
    __syncthreads();
    if (t < 3) {
        float mx = fmaxf(fmaxf(lg[0], lg[1]), lg[2]);
        float e0 = expf(lg[0] - mx), e1 = expf(lg[1] - mx), e2 = expf(lg[2] - mx);
        float ev = (t == 0) ? e0 : ((t == 1) ? e1 : e2);
        out[NGG * NCC + NGG * HIDD + g * NCC + t] = ev / (e0 + e1 + e2);  // preds
    }
}

// --------------------------------- host --------------------------------
extern "C" void kernel_launch(void* const* d_in, const int* in_sizes, int n_in,
                              void* d_out, int out_size)
{
    const float* x      = (const float*)d_in[0];
    const int*   ei     = (const int*)d_in[1];
    const int*   batch  = (const int*)d_in[2];
    const float* memory = (const float*)d_in[3];
    const float* enc_W  = (const float*)d_in[4];
    const float* enc_b  = (const float*)d_in[5];
    const float* gat_W  = (const float*)d_in[6];
    const float* att_s  = (const float*)d_in[7];
    const float* att_d  = (const float*)d_in[8];
    const float* gat_b  = (const float*)d_in[9];
    const float* W_ih   = (const float*)d_in[10];
    const float* W_hh   = (const float*)d_in[11];
    const float* b_ih   = (const float*)d_in[12];
    const float* b_hh   = (const float*)d_in[13];
    const float* c1W    = (const float*)d_in[14];
    const float* c1b    = (const float*)d_in[15];
    const float* c2W    = (const float*)d_in[16];
    const float* c2b    = (const float*)d_in[17];
    float* out = (float*)d_out;

    float *p_h, *p_z, *p_as, *p_ad, *p_q, *p_wt, *p_gi, *p_gh, *p_pool, *p_cnt;
    int *p_deg, *p_off, *p_cur, *p_esrc;
    cudaGetSymbolAddress((void**)&p_h,    g_h);
    cudaGetSymbolAddress((void**)&p_z,    g_z);
    cudaGetSymbolAddress((void**)&p_as,   g_as);
    cudaGetSymbolAddress((void**)&p_ad,   g_ad);
    cudaGetSymbolAddress((void**)&p_q,    g_q);
    cudaGetSymbolAddress((void**)&p_wt,   g_wt);
    cudaGetSymbolAddress((void**)&p_gi,   g_gi);
    cudaGetSymbolAddress((void**)&p_gh,   g_gh);
    cudaGetSymbolAddress((void**)&p_pool, g_pool);
    cudaGetSymbolAddress((void**)&p_cnt,  g_cnt);
    cudaGetSymbolAddress((void**)&p_deg,  g_deg);
    cudaGetSymbolAddress((void**)&p_off,  g_off);
    cudaGetSymbolAddress((void**)&p_cur,  g_cur);
    cudaGetSymbolAddress((void**)&p_esrc, g_esrc);

    const int MB = (NN + 127) / 128;   // 391

    // CSR build (once; reused by all 3 layers)
    cudaMemsetAsync(p_deg, 0, sizeof(int) * NN);
    cudaMemsetAsync(p_cur, 0, sizeof(int) * NN);
    csr_count<<<(ETOT + 255) / 256, 256>>>(ei, p_deg);
    csr_scan<<<1, 1024>>>(p_deg, p_off);
    csr_scatter<<<(ETOT + 255) / 256, 256>>>(ei, p_off, p_cur, p_esrc);

    // node encoder: h = relu(x @ enc_W + enc_b)
    gemm_db<false><<<dim3(1, MB), 256>>>(x, enc_W, enc_b, p_h, NN, 128, 128, 1.f, 1);

    for (int l = 0; l < NLL; l++) {
        const float* Wl = gat_W + (size_t)l * HIDD * NHH * HIDD;
        build_q<<<(2048 * 32 + 255) / 256, 256>>>(
            Wl, att_s + l * NHH * HIDD, att_d + l * NHH * HIDD, p_q);
        alpha2<<<(NN * 32 + 255) / 256, 256>>>(p_h, p_q, p_as, p_ad);
        build_wt<<<(NHH * HIDD * HIDD + 255) / 256, 256>>>(Wl, p_wt);
        edge_agg<<<NN, 128>>>(p_off, p_esrc, p_as, p_ad, p_h, p_z);
        // out = relu?( z @ Wt / 8 + bias )
        gemm_db<false><<<dim3(1, MB), 256>>>(
            p_z, p_wt, gat_b + l * HIDD, p_h, NN, NHH * HIDD, 128, 0.125f,
            (l < NLL - 1) ? 1 : 0);
    }

    // GRU
    gemm_db<true><<<dim3(3, MB), 256>>>(p_h,    W_ih, b_ih, p_gi, NN, 128, 384, 1.f, 0);
    gemm_db<true><<<dim3(3, MB), 256>>>(memory, W_hh, b_hh, p_gh, NN, 128, 384, 1.f, 0);
    gru_kernel<<<((size_t)NN * HIDD + 255) / 256, 256>>>(p_gi, p_gh, memory, p_h);

    // pooling + classifier
    cudaMemsetAsync(p_pool, 0, sizeof(float) * NGG * HIDD);
    cudaMemsetAsync(p_cnt,  0, sizeof(float) * NGG);
    pool_kernel<<<(NN + 499) / 500, 128>>>(p_h, batch, p_pool, p_cnt);
    classifier_kernel<<<NGG, HIDD>>>(p_pool, p_cnt, c1W, c1b, c2W, c2b, out);
}

// round 5
// speedup vs baseline: 1.6413x; 1.0038x over previous
#include <cuda_runtime.h>
#include <math.h>

#define NN   50000
#define EE   800000
#define ETOT (EE + NN)
#define HIDD 128
#define NHH  8
#define NLL  3
#define NGG  64
#define NCC  3

// ---------------- scratch (static device globals) ----------------
__device__ float g_h [(size_t)NN*HIDD];          // node features
__device__ float g_z [(size_t)NN*NHH*HIDD];      // aggregated z [N, 8*128]
__device__ float g_as[(size_t)NN*NHH];           // alpha_src
__device__ float g_ad[(size_t)NN*NHH];           // alpha_dst
__device__ float g_q [16*HIDD];                  // qT [16][128]
__device__ float g_wt[(size_t)NHH*HIDD*HIDD];    // Wt [1024,128]
__device__ float g_gi[(size_t)NN*3*HIDD];
__device__ float g_gh[(size_t)NN*3*HIDD];
__device__ float g_pool[NGG*HIDD];
__device__ float g_cnt [NGG];
__device__ int   g_deg [NN];
__device__ int   g_off [NN+1];
__device__ int   g_cur [NN];
__device__ int   g_esrc[ETOT];

// ---------------- CSR build (dst-grouped, src payload) ----------------
__global__ void csr_count(const int* __restrict__ ei, int* __restrict__ deg)
{
    int e = blockIdx.x * blockDim.x + threadIdx.x;
    if (e >= ETOT) return;
    int d = (e < EE) ? ei[EE + e] : (e - EE);
    atomicAdd(&deg[d], 1);
}

__global__ __launch_bounds__(1024) void csr_scan(const int* __restrict__ deg,
                                                 int* __restrict__ off)
{
    const int CHK = (NN + 1023) / 1024;   // 49
    int t = threadIdx.x;
    int lo = t * CHK, hi = min(lo + CHK, NN);
    int s = 0;
    for (int i = lo; i < hi; i++) s += deg[i];
    __shared__ int ps[1024];
    ps[t] = s; __syncthreads();
    for (int o = 1; o < 1024; o <<= 1) {
        int v = (t >= o) ? ps[t - o] : 0;
        __syncthreads();
        ps[t] += v;
        __syncthreads();
    }
    int run = (t > 0) ? ps[t - 1] : 0;
    for (int i = lo; i < hi; i++) { off[i] = run; run += deg[i]; }
    if (t == 1023) off[NN] = run;
}

__global__ void csr_scatter(const int* __restrict__ ei, const int* __restrict__ off,
                            int* __restrict__ cur, int* __restrict__ esrc)
{
    int e = blockIdx.x * blockDim.x + threadIdx.x;
    if (e >= ETOT) return;
    int s, d;
    if (e < EE) { s = ei[e]; d = ei[EE + e]; }
    else        { s = e - EE; d = s; }
    int p = atomicAdd(&cur[d], 1);
    esrc[off[d] + p] = s;
}

// ---------------- double-buffered SGEMM --------------------------------
// C[M,Nout] = relu?( scale * (A[M,K] @ B) + bias )
// BT=false: B[K,Nout]; BT=true: B[Nout,K]. BM=BN=128, BK=16, 256 thr, 8x8 micro.
template<bool BT>
__global__ __launch_bounds__(256) void gemm_db(
    const float* __restrict__ A, const float* __restrict__ B,
    const float* __restrict__ bias, float* __restrict__ C,
    int M, int K, int Nout, float scale, int relu)
{
    __shared__ float As[2][16][128];
    __shared__ float Bs[2][16][128];
    const int tid = threadIdx.x;
    const int tx = tid & 15, ty = tid >> 4;
    const int m0 = blockIdx.y * 128;
    const int n0 = blockIdx.x * 128;

    float acc[8][8];
    #pragma unroll
    for (int i = 0; i < 8; i++)
        #pragma unroll
        for (int j = 0; j < 8; j++) acc[i][j] = 0.f;

    float4 ra[2], rb[2];
    const int nst = K >> 4;

    // prologue: load stage 0
    #pragma unroll
    for (int j = 0; j < 2; j++) {
        int v = tid * 2 + j;
        int row = v >> 2, kq = v & 3;
        ra[j] = make_float4(0.f, 0.f, 0.f, 0.f);
        if (m0 + row < M) ra[j] = *(const float4*)(A + (size_t)(m0 + row) * K + kq * 4);
        if (BT) {
            rb[j] = *(const float4*)(B + (size_t)(n0 + row) * K + kq * 4);
        } else {
            int k = v >> 5, c = (v & 31) * 4;
            rb[j] = *(const float4*)(B + (size_t)k * Nout + n0 + c);
        }
    }
    #pragma unroll
    for (int j = 0; j < 2; j++) {
        int v = tid * 2 + j;
        int row = v >> 2, kq = v & 3;
        As[0][kq*4+0][row] = ra[j].x; As[0][kq*4+1][row] = ra[j].y;
        As[0][kq*4+2][row] = ra[j].z; As[0][kq*4+3][row] = ra[j].w;
        if (BT) {
            Bs[0][kq*4+0][row] = rb[j].x; Bs[0][kq*4+1][row] = rb[j].y;
            Bs[0][kq*4+2][row] = rb[j].z; Bs[0][kq*4+3][row] = rb[j].w;
        } else {
            int k = v >> 5, c = (v & 31) * 4;
            *(float4*)&Bs[0][k][c] = rb[j];
        }
    }
    __syncthreads();

    for (int s = 0; s < nst; s++) {
        const int buf = s & 1;
        if (s + 1 < nst) {
            int k0 = (s + 1) * 16;
            #pragma unroll
            for (int j = 0; j < 2; j++) {
                int v = tid * 2 + j;
                int row = v >> 2, kq = v & 3;
                ra[j] = make_float4(0.f, 0.f, 0.f, 0.f);
                if (m0 + row < M) ra[j] = *(const float4*)(A + (size_t)(m0 + row) * K + k0 + kq * 4);
                if (BT) {
                    rb[j] = *(const float4*)(B + (size_t)(n0 + row) * K + k0 + kq * 4);
                } else {
                    int k = v >> 5, c = (v & 31) * 4;
                    rb[j] = *(const float4*)(B + (size_t)(k0 + k) * Nout + n0 + c);
                }
            }
        }
        #pragma unroll
        for (int k = 0; k < 16; k++) {
            float a[8], b[8];
            float4 t;
            t = *(float4*)&As[buf][k][ty * 8];     a[0]=t.x; a[1]=t.y; a[2]=t.z; a[3]=t.w;
            t = *(float4*)&As[buf][k][ty * 8 + 4]; a[4]=t.x; a[5]=t.y; a[6]=t.z; a[7]=t.w;
            t = *(float4*)&Bs[buf][k][tx * 8];     b[0]=t.x; b[1]=t.y; b[2]=t.z; b[3]=t.w;
            t = *(float4*)&Bs[buf][k][tx * 8 + 4]; b[4]=t.x; b[5]=t.y; b[6]=t.z; b[7]=t.w;
            #pragma unroll
            for (int i = 0; i < 8; i++)
                #pragma unroll
                for (int j = 0; j < 8; j++)
                    acc[i][j] += a[i] * b[j];
        }
        if (s + 1 < nst) {
            const int nbuf = buf ^ 1;
            #pragma unroll
            for (int j = 0; j < 2; j++) {
                int v = tid * 2 + j;
                int row = v >> 2, kq = v & 3;
                As[nbuf][kq*4+0][row] = ra[j].x; As[nbuf][kq*4+1][row] = ra[j].y;
                As[nbuf][kq*4+2][row] = ra[j].z; As[nbuf][kq*4+3][row] = ra[j].w;
                if (BT) {
                    Bs[nbuf][kq*4+0][row] = rb[j].x; Bs[nbuf][kq*4+1][row] = rb[j].y;
                    Bs[nbuf][kq*4+2][row] = rb[j].z; Bs[nbuf][kq*4+3][row] = rb[j].w;
                } else {
                    int k = v >> 5, c = (v & 31) * 4;
                    *(float4*)&Bs[nbuf][k][c] = rb[j];
                }
            }
        }
        __syncthreads();
    }

    #pragma unroll
    for (int i = 0; i < 8; i++) {
        int row = m0 + ty * 8 + i;
        if (row >= M) continue;
        int col = n0 + tx * 8;
        float vb[8];
        #pragma unroll
        for (int j = 0; j < 8; j++) {
            float v = acc[i][j] * scale + (bias ? bias[col + j] : 0.f);
            if (relu) v = fmaxf(v, 0.f);
            vb[j] = v;
        }
        *(float4*)(C + (size_t)row * Nout + col)     = make_float4(vb[0], vb[1], vb[2], vb[3]);
        *(float4*)(C + (size_t)row * Nout + col + 4) = make_float4(vb[4], vb[5], vb[6], vb[7]);
    }
}

// ---------------- attention projection vectors -------------------------
// qT[j][k] (j<8: src head j, j>=8: dst head j-8) = sum_c W[k, h*128+c] * att[h,c]
__global__ void build_q(const float* __restrict__ W, const float* __restrict__ asrc,
                        const float* __restrict__ adst, float* __restrict__ qT)
{
    int w = (blockIdx.x * blockDim.x + threadIdx.x) >> 5;
    int lane = threadIdx.x & 31;
    if (w >= 2048) return;
    int j = w >> 7, k = w & 127;
    int h = j & 7;
    const float* att = ((j < 8) ? asrc : adst) + h * HIDD;
    const float* wr = W + (size_t)k * (NHH * HIDD) + h * HIDD;
    float4 a = *(const float4*)(wr + lane * 4);
    float4 b = *(const float4*)(att + lane * 4);
    float s = a.x*b.x + a.y*b.y + a.z*b.z + a.w*b.w;
    #pragma unroll
    for (int o = 16; o; o >>= 1) s += __shfl_xor_sync(0xffffffffu, s, o);
    if (lane == 0) qT[j * HIDD + k] = s;
}

// alpha = h @ qT^T : one warp per node, qT cached in smem as [16][128]
__global__ __launch_bounds__(256) void alpha2(const float* __restrict__ hf,
                                              const float* __restrict__ qT,
                                              float* __restrict__ as_, float* __restrict__ ad_)
{
    __shared__ float qs[16][HIDD];
    int t = threadIdx.x;
    for (int i = t; i < 16 * HIDD; i += 256) qs[i >> 7][i & 127] = qT[i];
    __syncthreads();
    int n = (blockIdx.x * 256 + t) >> 5;
    int lane = t & 31;
    if (n >= NN) return;
    float4 hv = *(const float4*)(hf + (size_t)n * HIDD + lane * 4);
    #pragma unroll
    for (int j = 0; j < 16; j++) {
        float4 qv = *(const float4*)&qs[j][lane * 4];
        float s = hv.x*qv.x + hv.y*qv.y + hv.z*qv.z + hv.w*qv.w;
        #pragma unroll
        for (int o = 16; o; o >>= 1) s += __shfl_xor_sync(0xffffffffu, s, o);
        if (lane == 0) {
            if (j < 8) as_[(size_t)n * 8 + j] = s;
            else       ad_[(size_t)n * 8 + (j - 8)] = s;
        }
    }
}

// Wt[h*128+k][c] = W[k][h*128+c]
__global__ void build_wt(const float* __restrict__ W, float* __restrict__ Wt)
{
    int idx = blockIdx.x * blockDim.x + threadIdx.x;
    if (idx >= NHH * HIDD * HIDD) return;
    int kk = idx >> 7, c = idx & 127;
    int h = kk >> 7, k = kk & 127;
    Wt[idx] = W[(size_t)k * (NHH * HIDD) + h * HIDD + c];
}

// ---------------- CSR edge aggregation: z[n,h,c] = sum_e softmax_w * h[src,c]
__global__ __launch_bounds__(128) void edge_agg(
    const int* __restrict__ off, const int* __restrict__ esrc,
    const float* __restrict__ as_, const float* __restrict__ ad_,
    const float* __restrict__ hf, float* __restrict__ zb)
{
    int n = blockIdx.x, t = threadIdx.x, h = t & 7;
    int e0 = off[n], e1 = off[n + 1];
    __shared__ float adn[8];
    __shared__ float den[8];
    __shared__ float red[16][8];
    __shared__ float ws[32][8];
    __shared__ int   ssm[32];
    if (t < 8) adn[t] = ad_[(size_t)n * 8 + t];
    __syncthreads();

    // denominators (exact softmax without max-shift: values are small)
    float part = 0.f;
    for (int i = e0 + (t >> 3); i < e1; i += 16) {
        int s = esrc[i];
        float v = as_[(size_t)s * 8 + h] + adn[h];
        v = v > 0.f ? v : 0.2f * v;
        part += __expf(v);
    }
    red[t >> 3][h] = part;
    __syncthreads();
    if (t < 8) {
        float x = 0.f;
        #pragma unroll
        for (int i = 0; i < 16; i++) x += red[i][t];
        den[t] = x;
    }
    __syncthreads();

    float z[8];
    #pragma unroll
    for (int i = 0; i < 8; i++) z[i] = 0.f;

    for (int c0 = e0; c0 < e1; c0 += 32) {
        int m = min(32, e1 - c0);
        for (int i = t >> 3; i < m; i += 16) {
            int s = esrc[c0 + i];
            if (h == 0) ssm[i] = s;
            float v = as_[(size_t)s * 8 + h] + adn[h];
            v = v > 0.f ? v : 0.2f * v;
            ws[i][h] = __expf(v) / (den[h] + 1e-16f);
        }
        __syncthreads();
        for (int i = 0; i < m; i++) {
            float val = hf[(size_t)ssm[i] * HIDD + t];
            #pragma unroll
            for (int hh = 0; hh < 8; hh++) z[hh] += ws[i][hh] * val;
        }
        __syncthreads();
    }
    float* zr = zb + (size_t)n * (NHH * HIDD) + t;
    #pragma unroll
    for (int hh = 0; hh < 8; hh++) zr[hh * HIDD] = z[hh];
}

// ---------------- GRU / pool / classifier ------------------------------
__global__ void gru_kernel(const float* __restrict__ gi, const float* __restrict__ gh,
                           const float* __restrict__ mem, float* __restrict__ hout)
{
    size_t i = (size_t)blockIdx.x * blockDim.x + threadIdx.x;
    if (i >= (size_t)NN * HIDD) return;
    size_t n = i >> 7; int c = (int)(i & 127);
    const float* a = gi + n * 384;
    const float* b = gh + n * 384;
    float r  = 1.f / (1.f + __expf(-(a[c]       + b[c])));
    float z  = 1.f / (1.f + __expf(-(a[128 + c] + b[128 + c])));
    float nc = tanhf(a[256 + c] + r * b[256 + c]);
    hout[i] = (1.f - z) * nc + z * mem[i];
}

__global__ void pool_kernel(const float* __restrict__ h, const int* __restrict__ batch,
                            float* __restrict__ sums, float* __restrict__ cnt)
{
    const int CHUNK = 500;
    int start = blockIdx.x * CHUNK;
    if (start >= NN) return;
    int end = min(start + CHUNK, NN);
    int c = threadIdx.x;
    int g = batch[start];
    float acc = 0.f, count = 0.f;
    for (int n = start; n < end; n++) {
        int bg = batch[n];
        if (bg != g) {
            atomicAdd(&sums[g * HIDD + c], acc);
            if (c == 0) atomicAdd(&cnt[g], count);
            acc = 0.f; count = 0.f; g = bg;
        }
        acc += h[(size_t)n * HIDD + c];
        count += 1.f;
    }
    atomicAdd(&sums[g * HIDD + c], acc);
    if (c == 0) atomicAdd(&cnt[g], count);
}

__global__ void classifier_kernel(const float* __restrict__ sums, const float* __restrict__ cnt,
                                  const float* __restrict__ c1W, const float* __restrict__ c1b,
                                  const float* __restrict__ c2W, const float* __restrict__ c2b,
                                  float* __restrict__ out)
{
    __shared__ float p[HIDD];
    __shared__ float hid[64];
    __shared__ float lg[3];
    int g = blockIdx.x, t = threadIdx.x;
    float c = fmaxf(cnt[g], 1.f);
    float pv = sums[g * HIDD + t] / c;
    p[t] = pv;
    out[NGG * NCC + g * HIDD + t] = pv;                       // pooled
    __syncthreads();
    if (t < 64) {
        float s = c1b[t];
        #pragma unroll 4
        for (int k = 0; k < HIDD; k++) s += p[k] * c1W[k * 64 + t];
        hid[t] = fmaxf(s, 0.f);
    }
    __syncthreads();
    if (t < 3) {
        float s = c2b[t];
        #pragma unroll 4
        for (int k = 0; k < 64; k++) s += hid[k] * c2W[k * 3 + t];
        lg[t] = s;
        out[g * NCC + t] = s;                                  // logits
    }
    __syncthreads();
    if (t < 3) {
        float mx = fmaxf(fmaxf(lg[0], lg[1]), lg[2]);
        float e0 = expf(lg[0] - mx), e1 = expf(lg[1] - mx), e2 = expf(lg[2] - mx);
        float ev = (t == 0) ? e0 : ((t == 1) ? e1 : e2);
        out[NGG * NCC + NGG * HIDD + g * NCC + t] = ev / (e0 + e1 + e2);  // preds
    }
}

// --------------------------------- host --------------------------------
extern "C" void kernel_launch(void* const* d_in, const int* in_sizes, int n_in,
                              void* d_out, int out_size)
{
    const float* x      = (const float*)d_in[0];
    const int*   ei     = (const int*)d_in[1];
    const int*   batch  = (const int*)d_in[2];
    const float* memory = (const float*)d_in[3];
    const float* enc_W  = (const float*)d_in[4];
    const float* enc_b  = (const float*)d_in[5];
    const float* gat_W  = (const float*)d_in[6];
    const float* att_s  = (const float*)d_in[7];
    const float* att_d  = (const float*)d_in[8];
    const float* gat_b  = (const float*)d_in[9];
    const float* W_ih   = (const float*)d_in[10];
    const float* W_hh   = (const float*)d_in[11];
    const float* b_ih   = (const float*)d_in[12];
    const float* b_hh   = (const float*)d_in[13];
    const float* c1W    = (const float*)d_in[14];
    const float* c1b    = (const float*)d_in[15];
    const float* c2W    = (const float*)d_in[16];
    const float* c2b    = (const float*)d_in[17];
    float* out = (float*)d_out;

    float *p_h, *p_z, *p_as, *p_ad, *p_q, *p_wt, *p_gi, *p_gh, *p_pool, *p_cnt;
    int *p_deg, *p_off, *p_cur, *p_esrc;
    cudaGetSymbolAddress((void**)&p_h,    g_h);
    cudaGetSymbolAddress((void**)&p_z,    g_z);
    cudaGetSymbolAddress((void**)&p_as,   g_as);
    cudaGetSymbolAddress((void**)&p_ad,   g_ad);
    cudaGetSymbolAddress((void**)&p_q,    g_q);
    cudaGetSymbolAddress((void**)&p_wt,   g_wt);
    cudaGetSymbolAddress((void**)&p_gi,   g_gi);
    cudaGetSymbolAddress((void**)&p_gh,   g_gh);
    cudaGetSymbolAddress((void**)&p_pool, g_pool);
    cudaGetSymbolAddress((void**)&p_cnt,  g_cnt);
    cudaGetSymbolAddress((void**)&p_deg,  g_deg);
    cudaGetSymbolAddress((void**)&p_off,  g_off);
    cudaGetSymbolAddress((void**)&p_cur,  g_cur);
    cudaGetSymbolAddress((void**)&p_esrc, g_esrc);

    const int MB = (NN + 127) / 128;   // 391

    // CSR build (once; reused by all 3 layers)
    cudaMemsetAsync(p_deg, 0, sizeof(int) * NN);
    cudaMemsetAsync(p_cur, 0, sizeof(int) * NN);
    csr_count<<<(ETOT + 255) / 256, 256>>>(ei, p_deg);
    csr_scan<<<1, 1024>>>(p_deg, p_off);
    csr_scatter<<<(ETOT + 255) / 256, 256>>>(ei, p_off, p_cur, p_esrc);

    // node encoder: h = relu(x @ enc_W + enc_b)
    gemm_db<false><<<dim3(1, MB), 256>>>(x, enc_W, enc_b, p_h, NN, 128, 128, 1.f, 1);

    for (int l = 0; l < NLL; l++) {
        const float* Wl = gat_W + (size_t)l * HIDD * NHH * HIDD;
        build_q<<<(2048 * 32 + 255) / 256, 256>>>(
            Wl, att_s + l * NHH * HIDD, att_d + l * NHH * HIDD, p_q);
        alpha2<<<(NN * 32 + 255) / 256, 256>>>(p_h, p_q, p_as, p_ad);
        build_wt<<<(NHH * HIDD * HIDD + 255) / 256, 256>>>(Wl, p_wt);
        edge_agg<<<NN, 128>>>(p_off, p_esrc, p_as, p_ad, p_h, p_z);
        // out = relu?( z @ Wt / 8 + bias )
        gemm_db<false><<<dim3(1, MB), 256>>>(
            p_z, p_wt, gat_b + l * HIDD, p_h, NN, NHH * HIDD, 128, 0.125f,
            (l < NLL - 1) ? 1 : 0);
    }

    // GRU
    gemm_db<true><<<dim3(3, MB), 256>>>(p_h,    W_ih, b_ih, p_gi, NN, 128, 384, 1.f, 0);
    gemm_db<true><<<dim3(3, MB), 256>>>(memory, W_hh, b_hh, p_gh, NN, 128, 384, 1.f, 0);
    gru_kernel<<<((size_t)NN * HIDD + 255) / 256, 256>>>(p_gi, p_gh, memory, p_h);

    // pooling + classifier
    cudaMemsetAsync(p_pool, 0, sizeof(float) * NGG * HIDD);
    cudaMemsetAsync(p_cnt,  0, sizeof(float) * NGG);
    pool_kernel<<<(NN + 499) / 500, 128>>>(p_h, batch, p_pool, p_cnt);
    classifier_kernel<<<NGG, HIDD>>>(p_pool, p_cnt, c1W, c1b, c2W, c2b, out);
}